// round 2
// baseline (speedup 1.0000x reference)
#include <cuda_runtime.h>
#include <math.h>

#define BB 8
#define CC 128
#define HH 96
#define WWD 96
#define EE 8
#define NG 4
#define PIX 9216   // 96*96

// ---------------- device globals (no allocations allowed) ----------------
__device__ float g_xgap[BB][CC];
__device__ float g_wt[NG][BB][EE];     // combine weight per (gate, batch, expert)
__device__ int   g_mask[EE][BB];       // 1 if (e,b) pair is selected by any gate
__device__ float g_beff[NG][BB][CC];   // effective bias sum_e w*bp
__device__ float g_u[(size_t)EE * BB * CC * PIX];  // squashed conv outputs (~302 MB)

// ---------------- K0: global average pool x -> g_xgap ----------------
__global__ void k_gap(const float* __restrict__ x) {
    int bc = blockIdx.x;                 // b*128 + c
    const float* p = x + (size_t)bc * PIX;
    float s = 0.f;
    for (int i = threadIdx.x; i < PIX; i += 256) s += p[i];
    __shared__ float red[8];
    #pragma unroll
    for (int o = 16; o; o >>= 1) s += __shfl_down_sync(0xffffffffu, s, o);
    if ((threadIdx.x & 31) == 0) red[threadIdx.x >> 5] = s;
    __syncthreads();
    if (threadIdx.x < 8) {
        s = red[threadIdx.x];
        #pragma unroll
        for (int o = 4; o; o >>= 1) s += __shfl_down_sync(0xffu, s, o);
        if (threadIdx.x == 0) g_xgap[bc >> 7][bc & 127] = s * (1.0f / PIX);
    }
}

// ---------------- K1: gating, top-2, combine weights, loss ----------------
__global__ void k_gate(const float* __restrict__ G, const float* __restrict__ bp,
                       float* __restrict__ dout) {
    __shared__ float probs[BB][EE];
    __shared__ float losses[NG];
    int t = threadIdx.x;
    if (t < EE * BB) g_mask[t / BB][t % BB] = 0;
    __syncthreads();

    for (int g = 0; g < NG; g++) {
        if (t < BB * EE) {
            int b = t >> 3, e = t & 7;
            float s = 0.f;
            for (int c = 0; c < CC; c++) s += g_xgap[b][c] * G[(g * CC + c) * EE + e];
            probs[b][e] = s;   // logits for now
        }
        __syncthreads();
        if (t < BB) {
            int b = t;
            float mx = probs[b][0];
            #pragma unroll
            for (int e = 1; e < EE; e++) mx = fmaxf(mx, probs[b][e]);
            float pr[EE]; float sum = 0.f;
            #pragma unroll
            for (int e = 0; e < EE; e++) { pr[e] = expf(probs[b][e] - mx); sum += pr[e]; }
            float inv = 1.f / sum;
            #pragma unroll
            for (int e = 0; e < EE; e++) { pr[e] *= inv; probs[b][e] = pr[e]; }
            // top-2 (stable: strict > keeps lowest index on tie, matching jax)
            int i0 = 0;
            #pragma unroll
            for (int e = 1; e < EE; e++) if (pr[e] > pr[i0]) i0 = e;
            int i1 = (i0 == 0) ? 1 : 0;
            #pragma unroll
            for (int e = 0; e < EE; e++) if (e != i0 && pr[e] > pr[i1]) i1 = e;
            // tw = softmax over the top-2 prob VALUES (reference softmaxes tv)
            float e1 = expf(pr[i1] - pr[i0]);
            float tw0 = 1.f / (1.f + e1), tw1 = e1 / (1.f + e1);
            #pragma unroll
            for (int e = 0; e < EE; e++) g_wt[g][b][e] = 0.f;
            g_wt[g][b][i0] = tw0; g_wt[g][b][i1] = tw1;
            g_mask[i0][b] = 1; g_mask[i1][b] = 1;
        }
        __syncthreads();
        if (t == 0) {
            float v[EE]; float mean = 0.f;
            #pragma unroll
            for (int e = 0; e < EE; e++) {
                float s = 0.f;
                for (int b = 0; b < BB; b++) s += probs[b][e];
                v[e] = s; mean += s;
            }
            mean *= (1.0f / EE);
            float var = 0.f;
            #pragma unroll
            for (int e = 0; e < EE; e++) { float d = v[e] - mean; var += d * d; }
            var *= (1.0f / (EE - 1));
            losses[g] = var / (mean * mean + 1e-10f);
        }
        __syncthreads();
    }
    // effective bias per (gate, batch, channel)
    if (t < CC) {
        for (int g = 0; g < NG; g++)
            for (int b = 0; b < BB; b++) {
                float s = 0.f;
                #pragma unroll
                for (int e = 0; e < EE; e++) s += g_wt[g][b][e] * bp[e * CC + t];
                g_beff[g][b][t] = s;
            }
    }
    if (t == 0)
        dout[(size_t)NG * BB * CC * PIX] =
            0.25f * (losses[0] + losses[1] + losses[2] + losses[3]);
}

// ---------------- K2: 3x3 conv + bias + relu + squash for selected pairs ----------------
// Block: 256 threads; tile = 8x8 pixels x all 128 output channels.
// Thread t: row r = t&7 (8 pixels wide), c_out group cog = t>>3 (4 channels).
__global__ void __launch_bounds__(256, 4) k_conv(const float* __restrict__ x,
                                                 const float* __restrict__ Wc,
                                                 const float* __restrict__ bc) {
    int e = blockIdx.z, b = blockIdx.y;
    if (!g_mask[e][b]) return;
    int th = blockIdx.x / 12, tw = blockIdx.x % 12;
    int h0 = th * 8, w0 = tw * 8;

    __shared__ float xs[8][10][13];     // 8 c_in x 10x10 halo, row pad 13
    __shared__ float ws2[128][73];      // [c_out][ci*9+tap], pad 73
    __shared__ float sn[64];            // per-pixel sum of squares

    int t = threadIdx.x;
    int r = t & 7, cog = t >> 3;

    float acc[4][8];
    #pragma unroll
    for (int i = 0; i < 4; i++)
        #pragma unroll
        for (int j = 0; j < 8; j++) acc[i][j] = 0.f;

    const float* xb = x + (size_t)b * CC * PIX;
    const float* wb = Wc + (size_t)e * CC * CC * 9;

    for (int cc = 0; cc < CC; cc += 8) {
        __syncthreads();
        // load x halo: 8 c_in x 10 x 10
        for (int i = t; i < 800; i += 256) {
            int ci = i / 100, rr = (i % 100) / 10, cl = i % 10;
            int hh = h0 + rr - 1, ww = w0 + cl - 1;
            float v = 0.f;
            if ((unsigned)hh < 96u && (unsigned)ww < 96u)
                v = xb[(size_t)(cc + ci) * PIX + hh * 96 + ww];
            xs[ci][rr][cl] = v;
        }
        // load weights: coalesced 72-float runs; conflict-free store (stride 1)
        for (int i = t; i < 9216; i += 256) {
            int co = i / 72, ct = i % 72;
            ws2[co][ct] = wb[(size_t)co * 1152 + cc * 9 + ct];
        }
        __syncthreads();
        #pragma unroll
        for (int ci = 0; ci < 8; ci++) {
            #pragma unroll
            for (int dh = 0; dh < 3; dh++) {
                float xr[10];
                #pragma unroll
                for (int k = 0; k < 10; k++) xr[k] = xs[ci][r + dh][k];
                #pragma unroll
                for (int dw = 0; dw < 3; dw++) {
                    int tap = ci * 9 + dh * 3 + dw;
                    float w0v = ws2[cog * 4 + 0][tap];
                    float w1v = ws2[cog * 4 + 1][tap];
                    float w2v = ws2[cog * 4 + 2][tap];
                    float w3v = ws2[cog * 4 + 3][tap];
                    #pragma unroll
                    for (int j = 0; j < 8; j++) {
                        float xv = xr[dw + j];
                        acc[0][j] += w0v * xv;
                        acc[1][j] += w1v * xv;
                        acc[2][j] += w2v * xv;
                        acc[3][j] += w3v * xv;
                    }
                }
            }
        }
    }

    // bias + relu + per-pixel channel sum-of-squares
    __syncthreads();
    if (t < 64) sn[t] = 0.f;
    __syncthreads();
    float bv[4];
    #pragma unroll
    for (int i = 0; i < 4; i++) bv[i] = bc[e * CC + cog * 4 + i];
    #pragma unroll
    for (int j = 0; j < 8; j++) {
        float p = 0.f;
        #pragma unroll
        for (int i = 0; i < 4; i++) {
            float v = fmaxf(acc[i][j] + bv[i], 0.f);
            acc[i][j] = v; p += v * v;
        }
        atomicAdd(&sn[r * 8 + j], p);
    }
    __syncthreads();

    float sc[8];
    #pragma unroll
    for (int j = 0; j < 8; j++) {
        float s = sn[r * 8 + j];
        sc[j] = s / (1.f + s) * rsqrtf(s + 1e-8f);
    }
    float* ub = g_u + (size_t)(e * BB + b) * CC * PIX;
    #pragma unroll
    for (int i = 0; i < 4; i++) {
        int c = cog * 4 + i;
        float* dst = ub + (size_t)c * PIX + (h0 + r) * 96 + w0;
        float4 v0 = make_float4(acc[i][0] * sc[0], acc[i][1] * sc[1],
                                acc[i][2] * sc[2], acc[i][3] * sc[3]);
        float4 v1 = make_float4(acc[i][4] * sc[4], acc[i][5] * sc[5],
                                acc[i][6] * sc[6], acc[i][7] * sc[7]);
        *(float4*)dst = v0;
        *(float4*)(dst + 4) = v1;
    }
}

// ---------------- K3: 1x1 conv + gate combine + bias, writes all 4 outputs ----------------
// Block: 256 threads, tile = 32 pixels x 128 out channels for one batch b.
// Thread: pg = t&15 (pixel pair), og = t>>4 (8 out channels).
__global__ void __launch_bounds__(256, 2) k_pw(const float* __restrict__ Wp,
                                               float* __restrict__ out) {
    int b = blockIdx.y;
    int pix0 = blockIdx.x * 32;
    __shared__ float su[64][32];
    __shared__ float swp[64][132];   // pad 132 keeps float4 rows aligned
    int t = threadIdx.x;
    int pg = t & 15, og = t >> 4;

    float accg[4][8][2];
    #pragma unroll
    for (int g = 0; g < 4; g++)
        #pragma unroll
        for (int i = 0; i < 8; i++) { accg[g][i][0] = 0.f; accg[g][i][1] = 0.f; }

    for (int e = 0; e < EE; e++) {
        if (!g_mask[e][b]) continue;   // uniform across block
        float y[8][2];
        #pragma unroll
        for (int i = 0; i < 8; i++) { y[i][0] = 0.f; y[i][1] = 0.f; }
        const float* ub = g_u + (size_t)(e * BB + b) * CC * PIX + pix0;
        const float* wpb = Wp + (size_t)e * CC * CC;
        for (int ch = 0; ch < 2; ch++) {
            int c0 = ch * 64;
            __syncthreads();
            for (int i = t; i < 2048; i += 256) {
                int ci = i >> 5, p = i & 31;
                su[ci][p] = ub[(size_t)(c0 + ci) * PIX + p];
            }
            for (int i = t; i < 8192; i += 256) {
                int o = i >> 6, ci = i & 63;
                swp[ci][o] = wpb[o * CC + c0 + ci];
            }
            __syncthreads();
            #pragma unroll 16
            for (int ci = 0; ci < 64; ci++) {
                float2 u2 = *(float2*)&su[ci][pg * 2];
                float4 wA = *(float4*)&swp[ci][og * 8];
                float4 wB = *(float4*)&swp[ci][og * 8 + 4];
                y[0][0] += wA.x * u2.x; y[0][1] += wA.x * u2.y;
                y[1][0] += wA.y * u2.x; y[1][1] += wA.y * u2.y;
                y[2][0] += wA.z * u2.x; y[2][1] += wA.z * u2.y;
                y[3][0] += wA.w * u2.x; y[3][1] += wA.w * u2.y;
                y[4][0] += wB.x * u2.x; y[4][1] += wB.x * u2.y;
                y[5][0] += wB.y * u2.x; y[5][1] += wB.y * u2.y;
                y[6][0] += wB.z * u2.x; y[6][1] += wB.z * u2.y;
                y[7][0] += wB.w * u2.x; y[7][1] += wB.w * u2.y;
            }
        }
        #pragma unroll
        for (int g = 0; g < 4; g++) {
            float w = g_wt[g][b][e];
            #pragma unroll
            for (int i = 0; i < 8; i++) {
                accg[g][i][0] += w * y[i][0];
                accg[g][i][1] += w * y[i][1];
            }
        }
    }
    #pragma unroll
    for (int g = 0; g < 4; g++) {
        #pragma unroll
        for (int i = 0; i < 8; i++) {
            int o = og * 8 + i;
            float be = g_beff[g][b][o];
            float2 v = make_float2(accg[g][i][0] + be, accg[g][i][1] + be);
            *(float2*)&out[(size_t)g * BB * CC * PIX + ((size_t)b * CC + o) * PIX +
                           pix0 + pg * 2] = v;
        }
    }
}

// ---------------- launch ----------------
extern "C" void kernel_launch(void* const* d_in, const int* in_sizes, int n_in,
                              void* d_out, int out_size) {
    const float* x  = (const float*)d_in[0];
    const float* G  = (const float*)d_in[1];
    const float* Wc = (const float*)d_in[2];
    const float* bc = (const float*)d_in[3];
    const float* Wp = (const float*)d_in[4];
    const float* bp = (const float*)d_in[5];
    float* out = (float*)d_out;

    k_gap<<<BB * CC, 256>>>(x);
    k_gate<<<1, 128>>>(G, bp, out);
    k_conv<<<dim3(144, BB, EE), 256>>>(x, Wc, bc);
    k_pw<<<dim3(PIX / 32, BB), 256>>>(Wp, out);
}